// round 2
// baseline (speedup 1.0000x reference)
#include <cuda_runtime.h>

// Problem constants
namespace {
constexpr int H  = 16;
constexpr int D  = 1024;
constexpr int DK = 64;
constexpr int DV = 64;
constexpr int B  = 4;
constexpr int SQ = 1024;
constexpr int SK = 1024;
constexpr float INV_SCALE = 1.0f / 32.0f;   // 1/sqrt(1024)
}

// Scratch (allocation-free rule: __device__ globals)
__device__ float g_q[B * H * SQ * DK];      // [b*H+h][s][k]
__device__ float g_k[B * H * SK * DK];
__device__ float g_v[B * H * SK * DV];
__device__ float g_ctx[B * SQ * H * DV];    // [b][q][h][v]  (concat-heads layout)

// ---------------------------------------------------------------------------
// Kernel 1: Q/K/V projections.  Per (proj, b, h): [1024 x 1024] @ [1024 x 64]
// NN GEMM, 64x64 tile, BK=16, 4x4 per thread.
// ---------------------------------------------------------------------------
__global__ __launch_bounds__(256) void proj_kernel(
    const float* __restrict__ query, const float* __restrict__ key,
    const float* __restrict__ value, const float* __restrict__ w_q,
    const float* __restrict__ w_k,   const float* __restrict__ w_v) {
  __shared__ float As[64 * 17];
  __shared__ float Bs[16 * 68];

  int z    = blockIdx.z;
  int proj = z / (B * H);
  int bh   = z - proj * (B * H);
  int b    = bh / H;
  int h    = bh % H;

  const float* X;
  const float* W;
  float* Out;
  if (proj == 0)      { X = query + (size_t)b * SQ * D; W = w_q + (size_t)h * D * DK; Out = g_q + (size_t)bh * SQ * DK; }
  else if (proj == 1) { X = key   + (size_t)b * SK * D; W = w_k + (size_t)h * D * DK; Out = g_k + (size_t)bh * SK * DK; }
  else                { X = value + (size_t)b * SK * D; W = w_v + (size_t)h * D * DV; Out = g_v + (size_t)bh * SK * DV; }

  int m0  = blockIdx.y * 64;
  int tid = threadIdx.x;
  int tx  = tid & 15, ty = tid >> 4;
  float acc[4][4] = {};

  for (int k0 = 0; k0 < D; k0 += 16) {
    #pragma unroll
    for (int i = tid; i < 1024; i += 256) {
      int m = i >> 4, kk = i & 15;
      As[m * 17 + kk] = X[(size_t)(m0 + m) * D + k0 + kk];
    }
    #pragma unroll
    for (int i = tid; i < 1024; i += 256) {
      int kk = i >> 6, n = i & 63;
      Bs[kk * 68 + n] = W[(size_t)(k0 + kk) * 64 + n];
    }
    __syncthreads();
    #pragma unroll
    for (int kk = 0; kk < 16; ++kk) {
      float a[4];
      #pragma unroll
      for (int i = 0; i < 4; ++i) a[i] = As[(ty * 4 + i) * 17 + kk];
      float4 bv = *reinterpret_cast<const float4*>(&Bs[kk * 68 + tx * 4]);
      #pragma unroll
      for (int i = 0; i < 4; ++i) {
        acc[i][0] += a[i] * bv.x;  acc[i][1] += a[i] * bv.y;
        acc[i][2] += a[i] * bv.z;  acc[i][3] += a[i] * bv.w;
      }
    }
    __syncthreads();
  }
  #pragma unroll
  for (int i = 0; i < 4; ++i) {
    float4 o = make_float4(acc[i][0], acc[i][1], acc[i][2], acc[i][3]);
    *reinterpret_cast<float4*>(&Out[(size_t)(m0 + ty * 4 + i) * 64 + tx * 4]) = o;
  }
}

// ---------------------------------------------------------------------------
// Kernel 2: scores = Q @ K^T / 32.   Per (b,h): [1024x64] @ [1024x64]^T.
// NT GEMM. Writes raw (pre-softmax) scores directly into the attns output
// region, laid out [h*B + b][q][s].
// ---------------------------------------------------------------------------
__global__ __launch_bounds__(256) void scores_kernel(float* __restrict__ attns) {
  __shared__ float As[64 * 17];
  __shared__ float Bs[64 * 17];

  int bh = blockIdx.z;
  int b  = bh / H, h = bh % H;
  const float* Qp = g_q + (size_t)bh * SQ * DK;
  const float* Kp = g_k + (size_t)bh * SK * DK;
  int m0 = blockIdx.y * 64, n0 = blockIdx.x * 64;
  int tid = threadIdx.x, tx = tid & 15, ty = tid >> 4;
  float acc[4][4] = {};

  for (int k0 = 0; k0 < DK; k0 += 16) {
    #pragma unroll
    for (int i = tid; i < 1024; i += 256) {
      int m = i >> 4, kk = i & 15;
      As[m * 17 + kk] = Qp[(size_t)(m0 + m) * DK + k0 + kk];
      Bs[m * 17 + kk] = Kp[(size_t)(n0 + m) * DK + k0 + kk];
    }
    __syncthreads();
    #pragma unroll
    for (int kk = 0; kk < 16; ++kk) {
      float a[4], bb[4];
      #pragma unroll
      for (int i = 0; i < 4; ++i) {
        a[i]  = As[(ty * 4 + i) * 17 + kk];
        bb[i] = Bs[(tx * 4 + i) * 17 + kk];
      }
      #pragma unroll
      for (int i = 0; i < 4; ++i)
        #pragma unroll
        for (int j = 0; j < 4; ++j) acc[i][j] += a[i] * bb[j];
    }
    __syncthreads();
  }

  float* outbase = attns + (size_t)(h * B + b) * SQ * SK;
  #pragma unroll
  for (int i = 0; i < 4; ++i) {
    float4 o = make_float4(acc[i][0] * INV_SCALE, acc[i][1] * INV_SCALE,
                           acc[i][2] * INV_SCALE, acc[i][3] * INV_SCALE);
    *reinterpret_cast<float4*>(&outbase[(size_t)(m0 + ty * 4 + i) * SK + n0 + tx * 4]) = o;
  }
}

// ---------------------------------------------------------------------------
// Kernel 3: in-place row softmax over the attns region. 1 block per row.
// ---------------------------------------------------------------------------
__global__ __launch_bounds__(256) void softmax_kernel(float* __restrict__ attns) {
  __shared__ float redm[8];
  __shared__ float reds[8];
  float* p = attns + (size_t)blockIdx.x * SK;
  int tid = threadIdx.x;

  float4 v = reinterpret_cast<float4*>(p)[tid];
  float mx = fmaxf(fmaxf(v.x, v.y), fmaxf(v.z, v.w));
  #pragma unroll
  for (int o = 16; o > 0; o >>= 1) mx = fmaxf(mx, __shfl_xor_sync(0xffffffffu, mx, o));
  if ((tid & 31) == 0) redm[tid >> 5] = mx;
  __syncthreads();
  float m_all = redm[0];
  #pragma unroll
  for (int i = 1; i < 8; ++i) m_all = fmaxf(m_all, redm[i]);

  v.x = __expf(v.x - m_all);
  v.y = __expf(v.y - m_all);
  v.z = __expf(v.z - m_all);
  v.w = __expf(v.w - m_all);
  float s = v.x + v.y + v.z + v.w;
  #pragma unroll
  for (int o = 16; o > 0; o >>= 1) s += __shfl_xor_sync(0xffffffffu, s, o);
  if ((tid & 31) == 0) reds[tid >> 5] = s;
  __syncthreads();
  float s_all = 0.f;
  #pragma unroll
  for (int i = 0; i < 8; ++i) s_all += reds[i];
  float inv = 1.0f / s_all;

  v.x *= inv; v.y *= inv; v.z *= inv; v.w *= inv;
  reinterpret_cast<float4*>(p)[tid] = v;
}

// ---------------------------------------------------------------------------
// Kernel 4: context = attn @ V.  Per (b,h): [1024x1024] @ [1024x64] (NN).
// Writes ctx in concat-heads layout [b][q][h][v].
// ---------------------------------------------------------------------------
__global__ __launch_bounds__(256) void av_kernel(const float* __restrict__ attns) {
  __shared__ float As[64 * 17];
  __shared__ float Bs[16 * 68];

  int bh = blockIdx.z;
  int b  = bh / H, h = bh % H;
  const float* A = attns + (size_t)(h * B + b) * SQ * SK;
  const float* V = g_v + (size_t)bh * SK * DV;
  int m0 = blockIdx.y * 64;
  int tid = threadIdx.x, tx = tid & 15, ty = tid >> 4;
  float acc[4][4] = {};

  for (int k0 = 0; k0 < SK; k0 += 16) {
    #pragma unroll
    for (int i = tid; i < 1024; i += 256) {
      int m = i >> 4, kk = i & 15;
      As[m * 17 + kk] = A[(size_t)(m0 + m) * SK + k0 + kk];
    }
    #pragma unroll
    for (int i = tid; i < 1024; i += 256) {
      int kk = i >> 6, n = i & 63;
      Bs[kk * 68 + n] = V[(size_t)(k0 + kk) * 64 + n];
    }
    __syncthreads();
    #pragma unroll
    for (int kk = 0; kk < 16; ++kk) {
      float a[4];
      #pragma unroll
      for (int i = 0; i < 4; ++i) a[i] = As[(ty * 4 + i) * 17 + kk];
      float4 bv = *reinterpret_cast<const float4*>(&Bs[kk * 68 + tx * 4]);
      #pragma unroll
      for (int i = 0; i < 4; ++i) {
        acc[i][0] += a[i] * bv.x;  acc[i][1] += a[i] * bv.y;
        acc[i][2] += a[i] * bv.z;  acc[i][3] += a[i] * bv.w;
      }
    }
    __syncthreads();
  }
  #pragma unroll
  for (int i = 0; i < 4; ++i) {
    size_t q = (size_t)(m0 + ty * 4 + i);
    float4 o = make_float4(acc[i][0], acc[i][1], acc[i][2], acc[i][3]);
    *reinterpret_cast<float4*>(&g_ctx[(((size_t)b * SQ + q) * H + h) * DV + tx * 4]) = o;
  }
}

// ---------------------------------------------------------------------------
// Kernel 5: out = ctx @ w_proj^T + b_proj.  [4096 x 1024] @ [1024 x 1024]^T (NT).
// ---------------------------------------------------------------------------
__global__ __launch_bounds__(256) void outproj_kernel(
    const float* __restrict__ w_proj, const float* __restrict__ b_proj,
    float* __restrict__ out) {
  __shared__ float As[64 * 17];
  __shared__ float Bs[64 * 17];

  const int K = H * DV;   // 1024
  int m0 = blockIdx.y * 64, n0 = blockIdx.x * 64;
  int tid = threadIdx.x, tx = tid & 15, ty = tid >> 4;
  float acc[4][4] = {};

  for (int k0 = 0; k0 < K; k0 += 16) {
    #pragma unroll
    for (int i = tid; i < 1024; i += 256) {
      int m = i >> 4, kk = i & 15;
      As[m * 17 + kk] = g_ctx[(size_t)(m0 + m) * K + k0 + kk];
      Bs[m * 17 + kk] = w_proj[(size_t)(n0 + m) * K + k0 + kk];
    }
    __syncthreads();
    #pragma unroll
    for (int kk = 0; kk < 16; ++kk) {
      float a[4], bb[4];
      #pragma unroll
      for (int i = 0; i < 4; ++i) {
        a[i]  = As[(ty * 4 + i) * 17 + kk];
        bb[i] = Bs[(tx * 4 + i) * 17 + kk];
      }
      #pragma unroll
      for (int i = 0; i < 4; ++i)
        #pragma unroll
        for (int j = 0; j < 4; ++j) acc[i][j] += a[i] * bb[j];
    }
    __syncthreads();
  }

  float4 bias = *reinterpret_cast<const float4*>(&b_proj[n0 + tx * 4]);
  #pragma unroll
  for (int i = 0; i < 4; ++i) {
    float4 o = make_float4(acc[i][0] + bias.x, acc[i][1] + bias.y,
                           acc[i][2] + bias.z, acc[i][3] + bias.w);
    *reinterpret_cast<float4*>(&out[(size_t)(m0 + ty * 4 + i) * D + n0 + tx * 4]) = o;
  }
}

// ---------------------------------------------------------------------------
extern "C" void kernel_launch(void* const* d_in, const int* in_sizes, int n_in,
                              void* d_out, int out_size) {
  const float* query  = (const float*)d_in[0];
  const float* key    = (const float*)d_in[1];
  const float* value  = (const float*)d_in[2];
  const float* w_q    = (const float*)d_in[3];
  const float* w_k    = (const float*)d_in[4];
  const float* w_v    = (const float*)d_in[5];
  const float* w_proj = (const float*)d_in[6];
  const float* b_proj = (const float*)d_in[7];

  float* out   = (float*)d_out;
  float* attns = out + (size_t)B * SQ * D;   // second output region

  // 1) Q/K/V projections
  proj_kernel<<<dim3(1, SQ / 64, 3 * B * H), 256>>>(query, key, value, w_q, w_k, w_v);
  // 2) raw scores into attns region
  scores_kernel<<<dim3(SK / 64, SQ / 64, B * H), 256>>>(attns);
  // 3) in-place softmax
  softmax_kernel<<<H * B * SQ, 256>>>(attns);
  // 4) attn @ V -> ctx (concat-heads layout)
  av_kernel<<<dim3(1, SQ / 64, B * H), 256>>>(attns);
  // 5) output projection + bias
  outproj_kernel<<<dim3(D / 64, (B * SQ) / 64, 1), 256>>>(w_proj, b_proj, out);
}

// round 3
// speedup vs baseline: 1.1600x; 1.1600x over previous
#include <cuda_runtime.h>

namespace {
constexpr int H  = 16;
constexpr int D  = 1024;
constexpr int DK = 64;
constexpr int DV = 64;
constexpr int B  = 4;
constexpr int SQ = 1024;
constexpr int SK = 1024;
constexpr float INV_SCALE = 1.0f / 32.0f;   // 1/sqrt(1024)
}

// Scratch (allocation-free rule: __device__ globals)
__device__ float g_q[B * H * SQ * DK];      // [(b*H+h)][s][k]
__device__ float g_k[B * H * SK * DK];
__device__ float g_v[B * H * SK * DV];
__device__ float g_ctx[B * SQ * H * DV];    // [b][q][h][v]  (concat-heads layout)

// ---------------------------------------------------------------------------
// Kernel 1: fused-head projections. Per (proj, b): GEMM M=1024, N=H*64=1024,
// K=1024.  128x128 tile, BK=16, 8x8 micro, 256 threads.
// B matrix column n -> head h=n>>6, col k=n&63 (w layout [h][d][64]).
// ---------------------------------------------------------------------------
__global__ __launch_bounds__(256) void proj_kernel(
    const float* __restrict__ query, const float* __restrict__ key,
    const float* __restrict__ value, const float* __restrict__ w_q,
    const float* __restrict__ w_k,   const float* __restrict__ w_v) {
  __shared__ float As[16][132];
  __shared__ float Bs[16][128];

  int z    = blockIdx.z;            // 0..11
  int proj = z >> 2;
  int b    = z & 3;

  const float* X; const float* W; float* OutBase;
  if (proj == 0)      { X = query + (size_t)b * SQ * D; W = w_q; OutBase = g_q; }
  else if (proj == 1) { X = key   + (size_t)b * SK * D; W = w_k; OutBase = g_k; }
  else                { X = value + (size_t)b * SK * D; W = w_v; OutBase = g_v; }

  int m0 = blockIdx.y * 128, n0 = blockIdx.x * 128;
  int t  = threadIdx.x;
  int tn = (t & 15) * 8, tm = (t >> 4) * 8;
  float acc[8][8] = {};

  for (int k0 = 0; k0 < D; k0 += 16) {
    // A tile 128x16 (transpose into As[k][m]); 2 float4 per thread
    #pragma unroll
    for (int i = 0; i < 2; ++i) {
      int f = t * 2 + i;
      int m = f >> 2, kq = (f & 3) * 4;
      float4 v = *reinterpret_cast<const float4*>(&X[(size_t)(m0 + m) * D + k0 + kq]);
      As[kq + 0][m] = v.x; As[kq + 1][m] = v.y;
      As[kq + 2][m] = v.z; As[kq + 3][m] = v.w;
    }
    // B tile 16x128; 2 float4 per thread (head-strided columns)
    #pragma unroll
    for (int i = 0; i < 2; ++i) {
      int f  = t * 2 + i;
      int kk = f >> 5, nq = (f & 31) * 4;
      int n  = n0 + nq;
      int h  = n >> 6, kc = n & 63;
      float4 v = *reinterpret_cast<const float4*>(&W[((size_t)h * D + (k0 + kk)) * 64 + kc]);
      *reinterpret_cast<float4*>(&Bs[kk][nq]) = v;
    }
    __syncthreads();
    #pragma unroll
    for (int kk = 0; kk < 16; ++kk) {
      float a[8], bb[8];
      *reinterpret_cast<float4*>(&a[0])  = *reinterpret_cast<float4*>(&As[kk][tm]);
      *reinterpret_cast<float4*>(&a[4])  = *reinterpret_cast<float4*>(&As[kk][tm + 4]);
      *reinterpret_cast<float4*>(&bb[0]) = *reinterpret_cast<float4*>(&Bs[kk][tn]);
      *reinterpret_cast<float4*>(&bb[4]) = *reinterpret_cast<float4*>(&Bs[kk][tn + 4]);
      #pragma unroll
      for (int i = 0; i < 8; ++i)
        #pragma unroll
        for (int j = 0; j < 8; ++j) acc[i][j] += a[i] * bb[j];
    }
    __syncthreads();
  }

  // store: n chunk of 8 stays within one head (64 | n boundaries, tn aligned 8)
  int n = n0 + tn;
  int h = n >> 6, kc = n & 63;
  float* Out = OutBase + ((size_t)(b * H + h) * SQ) * 64 + kc;
  #pragma unroll
  for (int i = 0; i < 8; ++i) {
    size_t row = (size_t)(m0 + tm + i) * 64;
    *reinterpret_cast<float4*>(&Out[row])     = make_float4(acc[i][0], acc[i][1], acc[i][2], acc[i][3]);
    *reinterpret_cast<float4*>(&Out[row + 4]) = make_float4(acc[i][4], acc[i][5], acc[i][6], acc[i][7]);
  }
}

// ---------------------------------------------------------------------------
// Kernel 2: scores = Q @ K^T / 32 (NT). Per bh: 1024x1024x64.
// 128x128 tile, BK=16 (4 iters), 8x8 micro. Writes raw scores into attns.
// ---------------------------------------------------------------------------
__global__ __launch_bounds__(256) void scores_kernel(float* __restrict__ attns) {
  __shared__ float As[16][132];
  __shared__ float Bs[16][132];

  int bh = blockIdx.z;
  int b  = bh / H, h = bh % H;
  const float* Qp = g_q + (size_t)bh * SQ * DK;
  const float* Kp = g_k + (size_t)bh * SK * DK;
  int m0 = blockIdx.y * 128, n0 = blockIdx.x * 128;
  int t  = threadIdx.x;
  int tn = (t & 15) * 8, tm = (t >> 4) * 8;
  float acc[8][8] = {};

  for (int k0 = 0; k0 < DK; k0 += 16) {
    #pragma unroll
    for (int i = 0; i < 2; ++i) {
      int f = t * 2 + i;
      int m = f >> 2, kq = (f & 3) * 4;
      float4 v = *reinterpret_cast<const float4*>(&Qp[(size_t)(m0 + m) * 64 + k0 + kq]);
      As[kq + 0][m] = v.x; As[kq + 1][m] = v.y;
      As[kq + 2][m] = v.z; As[kq + 3][m] = v.w;
    }
    #pragma unroll
    for (int i = 0; i < 2; ++i) {
      int f = t * 2 + i;
      int n = f >> 2, kq = (f & 3) * 4;
      float4 v = *reinterpret_cast<const float4*>(&Kp[(size_t)(n0 + n) * 64 + k0 + kq]);
      Bs[kq + 0][n] = v.x; Bs[kq + 1][n] = v.y;
      Bs[kq + 2][n] = v.z; Bs[kq + 3][n] = v.w;
    }
    __syncthreads();
    #pragma unroll
    for (int kk = 0; kk < 16; ++kk) {
      float a[8], bb[8];
      *reinterpret_cast<float4*>(&a[0])  = *reinterpret_cast<float4*>(&As[kk][tm]);
      *reinterpret_cast<float4*>(&a[4])  = *reinterpret_cast<float4*>(&As[kk][tm + 4]);
      *reinterpret_cast<float4*>(&bb[0]) = *reinterpret_cast<float4*>(&Bs[kk][tn]);
      *reinterpret_cast<float4*>(&bb[4]) = *reinterpret_cast<float4*>(&Bs[kk][tn + 4]);
      #pragma unroll
      for (int i = 0; i < 8; ++i)
        #pragma unroll
        for (int j = 0; j < 8; ++j) acc[i][j] += a[i] * bb[j];
    }
    __syncthreads();
  }

  float* outbase = attns + (size_t)(h * B + b) * SQ * SK;
  #pragma unroll
  for (int i = 0; i < 8; ++i) {
    size_t row = (size_t)(m0 + tm + i) * SK + n0 + tn;
    *reinterpret_cast<float4*>(&outbase[row]) =
        make_float4(acc[i][0] * INV_SCALE, acc[i][1] * INV_SCALE,
                    acc[i][2] * INV_SCALE, acc[i][3] * INV_SCALE);
    *reinterpret_cast<float4*>(&outbase[row + 4]) =
        make_float4(acc[i][4] * INV_SCALE, acc[i][5] * INV_SCALE,
                    acc[i][6] * INV_SCALE, acc[i][7] * INV_SCALE);
  }
}

// ---------------------------------------------------------------------------
// Kernel 3: in-place row softmax. 1 block per row.
// ---------------------------------------------------------------------------
__global__ __launch_bounds__(256) void softmax_kernel(float* __restrict__ attns) {
  __shared__ float redm[8];
  __shared__ float reds[8];
  float* p = attns + (size_t)blockIdx.x * SK;
  int tid = threadIdx.x;

  float4 v = reinterpret_cast<float4*>(p)[tid];
  float mx = fmaxf(fmaxf(v.x, v.y), fmaxf(v.z, v.w));
  #pragma unroll
  for (int o = 16; o > 0; o >>= 1) mx = fmaxf(mx, __shfl_xor_sync(0xffffffffu, mx, o));
  if ((tid & 31) == 0) redm[tid >> 5] = mx;
  __syncthreads();
  float m_all = redm[0];
  #pragma unroll
  for (int i = 1; i < 8; ++i) m_all = fmaxf(m_all, redm[i]);

  v.x = __expf(v.x - m_all);
  v.y = __expf(v.y - m_all);
  v.z = __expf(v.z - m_all);
  v.w = __expf(v.w - m_all);
  float s = v.x + v.y + v.z + v.w;
  #pragma unroll
  for (int o = 16; o > 0; o >>= 1) s += __shfl_xor_sync(0xffffffffu, s, o);
  if ((tid & 31) == 0) reds[tid >> 5] = s;
  __syncthreads();
  float s_all = 0.f;
  #pragma unroll
  for (int i = 0; i < 8; ++i) s_all += reds[i];
  float inv = 1.0f / s_all;

  v.x *= inv; v.y *= inv; v.z *= inv; v.w *= inv;
  reinterpret_cast<float4*>(p)[tid] = v;
}

// ---------------------------------------------------------------------------
// Kernel 4: context = attn @ V (NN). Per bh: 1024x64x1024.
// 128x64 tile, BK=16, 8x8 micro, 128 threads.
// ---------------------------------------------------------------------------
__global__ __launch_bounds__(128) void av_kernel(const float* __restrict__ attns) {
  __shared__ float As[16][132];
  __shared__ float Bs[16][64];

  int bh = blockIdx.z;
  int b  = bh / H, h = bh % H;
  const float* A = attns + (size_t)(h * B + b) * SQ * SK;
  const float* V = g_v + (size_t)bh * SK * DV;
  int m0 = blockIdx.y * 128;
  int t  = threadIdx.x;
  int tn = (t & 7) * 8, tm = (t >> 3) * 8;
  float acc[8][8] = {};

  for (int k0 = 0; k0 < SK; k0 += 16) {
    // A tile 128x16, transpose; 4 float4 per thread
    #pragma unroll
    for (int i = 0; i < 4; ++i) {
      int f = t * 4 + i;
      int m = f >> 2, kq = (f & 3) * 4;
      float4 v = *reinterpret_cast<const float4*>(&A[(size_t)(m0 + m) * SK + k0 + kq]);
      As[kq + 0][m] = v.x; As[kq + 1][m] = v.y;
      As[kq + 2][m] = v.z; As[kq + 3][m] = v.w;
    }
    // B tile 16x64; 2 float4 per thread
    #pragma unroll
    for (int i = 0; i < 2; ++i) {
      int f  = t * 2 + i;
      int kk = f >> 4, nq = (f & 15) * 4;
      *reinterpret_cast<float4*>(&Bs[kk][nq]) =
          *reinterpret_cast<const float4*>(&V[(size_t)(k0 + kk) * 64 + nq]);
    }
    __syncthreads();
    #pragma unroll
    for (int kk = 0; kk < 16; ++kk) {
      float a[8], bb[8];
      *reinterpret_cast<float4*>(&a[0])  = *reinterpret_cast<float4*>(&As[kk][tm]);
      *reinterpret_cast<float4*>(&a[4])  = *reinterpret_cast<float4*>(&As[kk][tm + 4]);
      *reinterpret_cast<float4*>(&bb[0]) = *reinterpret_cast<float4*>(&Bs[kk][tn]);
      *reinterpret_cast<float4*>(&bb[4]) = *reinterpret_cast<float4*>(&Bs[kk][tn + 4]);
      #pragma unroll
      for (int i = 0; i < 8; ++i)
        #pragma unroll
        for (int j = 0; j < 8; ++j) acc[i][j] += a[i] * bb[j];
    }
    __syncthreads();
  }
  #pragma unroll
  for (int i = 0; i < 8; ++i) {
    size_t q = (size_t)(m0 + tm + i);
    float* dst = &g_ctx[(((size_t)b * SQ + q) * H + h) * DV + tn];
    *reinterpret_cast<float4*>(&dst[0]) = make_float4(acc[i][0], acc[i][1], acc[i][2], acc[i][3]);
    *reinterpret_cast<float4*>(&dst[4]) = make_float4(acc[i][4], acc[i][5], acc[i][6], acc[i][7]);
  }
}

// ---------------------------------------------------------------------------
// Kernel 5: out = ctx @ w_proj^T + b_proj (NT). 4096x1024x1024.
// 128x128 tile, BK=16, 8x8 micro, 256 threads.
// ---------------------------------------------------------------------------
__global__ __launch_bounds__(256) void outproj_kernel(
    const float* __restrict__ w_proj, const float* __restrict__ b_proj,
    float* __restrict__ out) {
  __shared__ float As[16][132];
  __shared__ float Bs[16][132];

  const int K = H * DV;   // 1024
  int m0 = blockIdx.y * 128, n0 = blockIdx.x * 128;
  int t  = threadIdx.x;
  int tn = (t & 15) * 8, tm = (t >> 4) * 8;
  float acc[8][8] = {};

  for (int k0 = 0; k0 < K; k0 += 16) {
    #pragma unroll
    for (int i = 0; i < 2; ++i) {
      int f = t * 2 + i;
      int m = f >> 2, kq = (f & 3) * 4;
      float4 v = *reinterpret_cast<const float4*>(&g_ctx[(size_t)(m0 + m) * K + k0 + kq]);
      As[kq + 0][m] = v.x; As[kq + 1][m] = v.y;
      As[kq + 2][m] = v.z; As[kq + 3][m] = v.w;
    }
    #pragma unroll
    for (int i = 0; i < 2; ++i) {
      int f = t * 2 + i;
      int n = f >> 2, kq = (f & 3) * 4;
      float4 v = *reinterpret_cast<const float4*>(&w_proj[(size_t)(n0 + n) * K + k0 + kq]);
      Bs[kq + 0][n] = v.x; Bs[kq + 1][n] = v.y;
      Bs[kq + 2][n] = v.z; Bs[kq + 3][n] = v.w;
    }
    __syncthreads();
    #pragma unroll
    for (int kk = 0; kk < 16; ++kk) {
      float a[8], bb[8];
      *reinterpret_cast<float4*>(&a[0])  = *reinterpret_cast<float4*>(&As[kk][tm]);
      *reinterpret_cast<float4*>(&a[4])  = *reinterpret_cast<float4*>(&As[kk][tm + 4]);
      *reinterpret_cast<float4*>(&bb[0]) = *reinterpret_cast<float4*>(&Bs[kk][tn]);
      *reinterpret_cast<float4*>(&bb[4]) = *reinterpret_cast<float4*>(&Bs[kk][tn + 4]);
      #pragma unroll
      for (int i = 0; i < 8; ++i)
        #pragma unroll
        for (int j = 0; j < 8; ++j) acc[i][j] += a[i] * bb[j];
    }
    __syncthreads();
  }

  float4 bias0 = *reinterpret_cast<const float4*>(&b_proj[n0 + tn]);
  float4 bias1 = *reinterpret_cast<const float4*>(&b_proj[n0 + tn + 4]);
  #pragma unroll
  for (int i = 0; i < 8; ++i) {
    size_t row = (size_t)(m0 + tm + i) * D + n0 + tn;
    *reinterpret_cast<float4*>(&out[row]) =
        make_float4(acc[i][0] + bias0.x, acc[i][1] + bias0.y,
                    acc[i][2] + bias0.z, acc[i][3] + bias0.w);
    *reinterpret_cast<float4*>(&out[row + 4]) =
        make_float4(acc[i][4] + bias1.x, acc[i][5] + bias1.y,
                    acc[i][6] + bias1.z, acc[i][7] + bias1.w);
  }
}

// ---------------------------------------------------------------------------
extern "C" void kernel_launch(void* const* d_in, const int* in_sizes, int n_in,
                              void* d_out, int out_size) {
  const float* query  = (const float*)d_in[0];
  const float* key    = (const float*)d_in[1];
  const float* value  = (const float*)d_in[2];
  const float* w_q    = (const float*)d_in[3];
  const float* w_k    = (const float*)d_in[4];
  const float* w_v    = (const float*)d_in[5];
  const float* w_proj = (const float*)d_in[6];
  const float* b_proj = (const float*)d_in[7];

  float* out   = (float*)d_out;
  float* attns = out + (size_t)B * SQ * D;   // second output region

  proj_kernel<<<dim3(8, 8, 12), 256>>>(query, key, value, w_q, w_k, w_v);
  scores_kernel<<<dim3(8, 8, B * H), 256>>>(attns);
  softmax_kernel<<<H * B * SQ, 256>>>(attns);
  av_kernel<<<dim3(1, 8, B * H), 128>>>(attns);
  outproj_kernel<<<dim3(8, 32, 1), 256>>>(w_proj, b_proj, out);
}